// round 12
// baseline (speedup 1.0000x reference)
#include <cuda_runtime.h>
#include <cuda_bf16.h>
#include <cstdint>

// ---------------------------------------------------------------------------
// Problem constants
// ---------------------------------------------------------------------------
#define B_SZ     2
#define L_SEQ    2048
#define D_MODEL  2048
#define N_HEADS  16
#define D_HEAD   128
#define HEAD_V   256
#define KEY_DIM  2048
#define VALUE_DIM 4096
#define TOTAL_PROJ 12320
#define CONV_CH  8192
#define BL       (B_SZ * L_SEQ)    // 4096

#define NCHUNK   8
#define CL       (L_SEQ / NCHUNK)  // 256 timesteps per chunk

// ---------------------------------------------------------------------------
// Scratch (static device globals)
// ---------------------------------------------------------------------------
__device__ float g_proj[(size_t)BL * TOTAL_PROJ];
__device__ float g_y[(size_t)BL * CONV_CH];
__device__ float g_eg[BL * N_HEADS];
__device__ float g_beta[BL * N_HEADS];
__device__ float g_S[128 * 256 * 32];          // recurrence state between chunks

__device__ __nv_bfloat16 g_Ah[(size_t)BL * D_MODEL];
__device__ __nv_bfloat16 g_Al[(size_t)BL * D_MODEL];
__device__ __nv_bfloat16 g_Bh[(size_t)D_MODEL * TOTAL_PROJ];
__device__ __nv_bfloat16 g_Bl[(size_t)D_MODEL * TOTAL_PROJ];

// ---------------------------------------------------------------------------
// Helpers
// ---------------------------------------------------------------------------
__device__ __forceinline__ uint32_t smem_u32(const void* p) {
    return (uint32_t)__cvta_generic_to_shared(p);
}
__device__ __forceinline__ void ldsm_x4(uint32_t& r0, uint32_t& r1,
                                        uint32_t& r2, uint32_t& r3, uint32_t a) {
    asm volatile("ldmatrix.sync.aligned.m8n8.x4.shared.b16 {%0,%1,%2,%3},[%4];\n"
                 : "=r"(r0), "=r"(r1), "=r"(r2), "=r"(r3) : "r"(a));
}
__device__ __forceinline__ void ldsm_x4_t(uint32_t& r0, uint32_t& r1,
                                          uint32_t& r2, uint32_t& r3, uint32_t a) {
    asm volatile("ldmatrix.sync.aligned.m8n8.x4.trans.shared.b16 {%0,%1,%2,%3},[%4];\n"
                 : "=r"(r0), "=r"(r1), "=r"(r2), "=r"(r3) : "r"(a));
}
__device__ __forceinline__ void mma_bf16(float* c, const uint32_t* a, const uint32_t* b) {
    asm volatile("mma.sync.aligned.m16n8k16.row.col.f32.bf16.bf16.f32 "
                 "{%0,%1,%2,%3},{%4,%5,%6,%7},{%8,%9},{%0,%1,%2,%3};\n"
                 : "+f"(c[0]), "+f"(c[1]), "+f"(c[2]), "+f"(c[3])
                 : "r"(a[0]), "r"(a[1]), "r"(a[2]), "r"(a[3]),
                   "r"(b[0]), "r"(b[1]));
}
__device__ __forceinline__ uint32_t pack_hi2(float x0, float x1) {
    return __byte_perm(__float_as_uint(x0), __float_as_uint(x1), 0x7632);
}
__device__ __forceinline__ uint32_t pack_lo2(float x0, float x1) {
    float h0 = __uint_as_float(__float_as_uint(x0) & 0xffff0000u);
    float h1 = __uint_as_float(__float_as_uint(x1) & 0xffff0000u);
    __nv_bfloat162 l2 = __float22bfloat162_rn(make_float2(x0 - h0, x1 - h1));
    return *reinterpret_cast<uint32_t*>(&l2);
}
__device__ __forceinline__ void cp16(uint32_t dst, const void* src) {
    asm volatile("cp.async.cg.shared.global [%0], [%1], 16;\n" :: "r"(dst), "l"(src));
}
__device__ __forceinline__ void cp4(uint32_t dst, const void* src) {
    asm volatile("cp.async.ca.shared.global [%0], [%1], 4;\n" :: "r"(dst), "l"(src));
}

// ---------------------------------------------------------------------------
// Kernel 0: split fp32 -> bf16 hi/lo for A and B
// ---------------------------------------------------------------------------
#define NA4 ((size_t)BL * D_MODEL / 4)
#define NB4 ((size_t)D_MODEL * TOTAL_PROJ / 4)
__global__ __launch_bounds__(256) void split_kernel(
    const float* __restrict__ A, const float* __restrict__ Bm)
{
    const size_t total = NA4 + NB4;
    for (size_t i = (size_t)blockIdx.x * blockDim.x + threadIdx.x;
         i < total; i += (size_t)gridDim.x * blockDim.x) {
        if (i < NA4) {
            float4 v = ((const float4*)A)[i];
            ((uint2*)g_Ah)[i] = make_uint2(pack_hi2(v.x, v.y), pack_hi2(v.z, v.w));
            ((uint2*)g_Al)[i] = make_uint2(pack_lo2(v.x, v.y), pack_lo2(v.z, v.w));
        } else {
            size_t j = i - NA4;
            float4 v = ((const float4*)Bm)[j];
            ((uint2*)g_Bh)[j] = make_uint2(pack_hi2(v.x, v.y), pack_hi2(v.z, v.w));
            ((uint2*)g_Bl)[j] = make_uint2(pack_lo2(v.x, v.y), pack_lo2(v.z, v.w));
        }
    }
}

// ---------------------------------------------------------------------------
// Kernel 1: GEMM chunk. grid (4, 97): x -> {batch, half} of this chunk's rows.
// ---------------------------------------------------------------------------
#define STAGES 4
#define AST 24
#define BST 136
#define A_BYTES (128 * AST * 2)
#define B_BYTES (16 * BST * 2)
#define STAGE_BYTES (2 * A_BYTES + 2 * B_BYTES)
#define SMEM_TOTAL_GEMM (STAGES * STAGE_BYTES)

__global__ __launch_bounds__(256) void mma_gemm_kernel(int chunk)
{
    const int N = TOTAL_PROJ, K = D_MODEL;
    extern __shared__ __align__(16) char smem_raw[];

    const int tid  = threadIdx.x;
    const int lane = tid & 31;
    const int warp = tid >> 5;
    const int wm   = warp & 1;
    const int wn   = warp >> 1;
    const int batch = blockIdx.x >> 1;
    const int mrow0 = batch * L_SEQ + chunk * CL + (blockIdx.x & 1) * 128;
    const int colBase = blockIdx.y * 128;

    const int ar = tid >> 1;
    const int ac = (tid & 1) << 3;
    const int br = tid >> 4;
    const int bc = (tid & 15) << 3;
    const bool bvalid = (colBase + bc) < N;

    auto sAh = [&](int s) { return (__nv_bfloat16*)(smem_raw + s * STAGE_BYTES); };
    auto sAl = [&](int s) { return (__nv_bfloat16*)(smem_raw + s * STAGE_BYTES + A_BYTES); };
    auto sBh = [&](int s) { return (__nv_bfloat16*)(smem_raw + s * STAGE_BYTES + 2 * A_BYTES); };
    auto sBl = [&](int s) { return (__nv_bfloat16*)(smem_raw + s * STAGE_BYTES + 2 * A_BYTES + B_BYTES); };

    auto copy_stage = [&](int s, int kt) {
        const int k0 = kt * 16;
        cp16(smem_u32(sAh(s) + ar * AST + ac), g_Ah + (size_t)(mrow0 + ar) * K + k0 + ac);
        cp16(smem_u32(sAl(s) + ar * AST + ac), g_Al + (size_t)(mrow0 + ar) * K + k0 + ac);
        if (bvalid) {
            cp16(smem_u32(sBh(s) + br * BST + bc), g_Bh + (size_t)(k0 + br) * N + colBase + bc);
            cp16(smem_u32(sBl(s) + br * BST + bc), g_Bl + (size_t)(k0 + br) * N + colBase + bc);
        } else {
            uint4 z = make_uint4(0, 0, 0, 0);
            *(uint4*)(sBh(s) + br * BST + bc) = z;
            *(uint4*)(sBl(s) + br * BST + bc) = z;
        }
    };

    float acc[4][4][4];
#pragma unroll
    for (int mt = 0; mt < 4; mt++)
#pragma unroll
        for (int nt = 0; nt < 4; nt++)
#pragma unroll
            for (int r = 0; r < 4; r++) acc[mt][nt][r] = 0.f;

    const int KT = K / 16;
#pragma unroll
    for (int s = 0; s < STAGES - 1; s++) {
        copy_stage(s, s);
        asm volatile("cp.async.commit_group;\n" ::: "memory");
    }

    const int m8 = lane >> 3;
    const int j8 = lane & 7;

    for (int kt = 0; kt < KT; kt++) {
        asm volatile("cp.async.wait_group %0;\n" :: "n"(STAGES - 2) : "memory");
        __syncthreads();

        const int nk = kt + STAGES - 1;
        if (nk < KT) copy_stage(nk & (STAGES - 1), nk);
        asm volatile("cp.async.commit_group;\n" ::: "memory");

        const int buf = kt & (STAGES - 1);
        const __nv_bfloat16* Ahs = sAh(buf);
        const __nv_bfloat16* Als = sAl(buf);
        const __nv_bfloat16* Bhs = sBh(buf);
        const __nv_bfloat16* Bls = sBl(buf);

        uint32_t ah[4][4], al[4][4], bh[4][2], bl[4][2];
#pragma unroll
        for (int mt = 0; mt < 4; mt++) {
            const int row = wm * 64 + mt * 16 + (m8 & 1) * 8 + j8;
            const int kc  = (m8 >> 1) * 8;
            ldsm_x4(ah[mt][0], ah[mt][1], ah[mt][2], ah[mt][3],
                    smem_u32(Ahs + row * AST + kc));
            ldsm_x4(al[mt][0], al[mt][1], al[mt][2], al[mt][3],
                    smem_u32(Als + row * AST + kc));
        }
#pragma unroll
        for (int nt2 = 0; nt2 < 2; nt2++) {
            const int kk = (m8 & 1) * 8 + j8;
            const int nn = wn * 32 + nt2 * 16 + (m8 >> 1) * 8;
            uint32_t r0, r1, r2, r3;
            ldsm_x4_t(r0, r1, r2, r3, smem_u32(Bhs + kk * BST + nn));
            bh[nt2 * 2][0] = r0; bh[nt2 * 2][1] = r1;
            bh[nt2 * 2 + 1][0] = r2; bh[nt2 * 2 + 1][1] = r3;
            ldsm_x4_t(r0, r1, r2, r3, smem_u32(Bls + kk * BST + nn));
            bl[nt2 * 2][0] = r0; bl[nt2 * 2][1] = r1;
            bl[nt2 * 2 + 1][0] = r2; bl[nt2 * 2 + 1][1] = r3;
        }

#pragma unroll
        for (int mt = 0; mt < 4; mt++)
#pragma unroll
            for (int nt = 0; nt < 4; nt++) {
                mma_bf16(acc[mt][nt], al[mt], bh[nt]);
                mma_bf16(acc[mt][nt], ah[mt], bl[nt]);
                mma_bf16(acc[mt][nt], ah[mt], bh[nt]);
            }
        __syncthreads();
    }

    const int g4 = lane >> 2;
    const int tg = lane & 3;
#pragma unroll
    for (int mt = 0; mt < 4; mt++) {
        const int row0 = mrow0 + wm * 64 + mt * 16 + g4;
        float* C0 = g_proj + (size_t)row0 * N;
        float* C1 = g_proj + (size_t)(row0 + 8) * N;
#pragma unroll
        for (int nt = 0; nt < 4; nt++) {
            const int col = colBase + wn * 32 + nt * 8 + tg * 2;
            if (col < N) {
                *(float2*)(C0 + col) = make_float2(acc[mt][nt][0], acc[mt][nt][1]);
                *(float2*)(C1 + col) = make_float2(acc[mt][nt][2], acc[mt][nt][3]);
            }
        }
    }
}

// ---------------------------------------------------------------------------
// Kernel 2: per-(b,l,h) scalars for one chunk (2*CL rows)
// ---------------------------------------------------------------------------
__global__ void scalars_kernel(const float* __restrict__ A_log,
                               const float* __restrict__ dt_bias, int chunk)
{
    int i = blockIdx.x * blockDim.x + threadIdx.x;
    if (i >= B_SZ * CL * N_HEADS) return;
    int r = i >> 4;                       // 0..511
    int h = i & 15;
    int batch = r >> 8;                   // r / CL
    int bl = batch * L_SEQ + chunk * CL + (r & (CL - 1));
    const float* row = g_proj + (size_t)bl * TOTAL_PROJ;
    float bv = row[12288 + h];
    g_beta[bl * N_HEADS + h] = 1.f / (1.f + expf(-bv));
    float a = row[12304 + h] + dt_bias[h];
    float sp = (a > 15.f) ? a : log1pf(expf(a));
    float g = -expf(A_log[h]) * sp;
    g_eg[bl * N_HEADS + h] = expf(g);
}

// ---------------------------------------------------------------------------
// Kernel 3: conv chunk. grid (64, 2*CL/CTILE)
// ---------------------------------------------------------------------------
#define CTILE 8
__global__ __launch_bounds__(128) void conv_kernel(const float* __restrict__ Wconv,
                                                   int chunk)
{
    const int grp  = blockIdx.x;
    const int tile = blockIdx.y;                      // 0..63
    const int b    = tile / (CL / CTILE);
    const int l0   = chunk * CL + (tile % (CL / CTILE)) * CTILE;
    const int c    = grp * 128 + threadIdx.x;
    const int lane = threadIdx.x & 31;
    const int wid  = threadIdx.x >> 5;

    const float* w = Wconv + c * 4;
    const float w0 = w[0], w1 = w[1], w2 = w[2], w3 = w[3];

    const float* pbase = g_proj + ((size_t)(b * L_SEQ + l0)) * TOTAL_PROJ + c;
    float xv[CTILE + 3];
#pragma unroll
    for (int j = 0; j < CTILE + 3; j++) {
        const int l = l0 - 3 + j;
        xv[j] = (l >= 0) ? pbase[(ptrdiff_t)(j - 3) * TOTAL_PROJ] : 0.f;
    }

    __shared__ float red[4];
    float* yrow = g_y + ((size_t)(b * L_SEQ + l0)) * CONV_CH + c;

#pragma unroll
    for (int t = 0; t < CTILE; t++) {
        float acc = xv[t] * w0 + xv[t + 1] * w1 + xv[t + 2] * w2 + xv[t + 3] * w3;
        float s = acc / (1.f + expf(-acc));
        float val = s;
        if (grp < 32) {
            float ss = s * s;
#pragma unroll
            for (int off = 16; off > 0; off >>= 1)
                ss += __shfl_xor_sync(0xffffffffu, ss, off);
            if (lane == 0) red[wid] = ss;
            __syncthreads();
            float tot = red[0] + red[1] + red[2] + red[3];
            val = s * rsqrtf(tot + 1e-6f);
            __syncthreads();
        }
        yrow[(size_t)t * CONV_CH] = val;
    }
}

// ---------------------------------------------------------------------------
// Kernel 4: recurrence chunk (CL steps); S persists in g_S between chunks.
// ---------------------------------------------------------------------------
#define RGROUPS 3
#define GSTEPS  4
#define RSTAGES (RGROUPS * GSTEPS)
#define RSTRIDE 420
#define NGROUPS_C (CL / GSTEPS)   // 64

__global__ __launch_bounds__(256, 1) void recurrence_kernel(float* __restrict__ out,
                                                            int chunk)
{
    const int slice = blockIdx.x & 3;
    const int bh    = blockIdx.x >> 2;
    const int b     = bh >> 4;
    const int h     = bh & 15;
    const int tid   = threadIdx.x;
    const int col   = tid >> 2;
    const int kp    = tid & 3;
    const int vcol  = slice * 64 + col;

    __shared__ __align__(16) float ring[RSTAGES * RSTRIDE];

    float S[32];
    float4* Sg = (float4*)(g_S + ((size_t)(blockIdx.x * 256 + tid)) * 32);
    if (chunk == 0) {
#pragma unroll
        for (int j = 0; j < 32; j++) S[j] = 0.f;
    } else {
#pragma unroll
        for (int u = 0; u < 8; u++) {
            float4 v = Sg[u];
            S[u * 4 + 0] = v.x; S[u * 4 + 1] = v.y;
            S[u * 4 + 2] = v.z; S[u * 4 + 3] = v.w;
        }
    }

    const float scale = 0.08838834764831845f;

    const size_t ybase = (size_t)b * L_SEQ * CONV_CH;
    const size_t pbase = (size_t)b * L_SEQ * TOTAL_PROJ;
    const int qofs  = h * 128;
    const int kofs  = KEY_DIM + h * 128;
    const int vofs0 = 2 * KEY_DIM + h * 256 + slice * 64;
    const int gofs0 = 2 * KEY_DIM + VALUE_DIM + h * 256 + slice * 64;
    const int ghofs = (b * L_SEQ) * N_HEADS + h;
    const int t0 = chunk * CL;

    const uint32_t ring_u32 = smem_u32(ring);

    auto slot_of = [&](int t) -> int {
        return ((t >> 2) % RGROUPS) * GSTEPS + (t & 3);
    };

    auto issue_stage = [&](int t) {
        const uint32_t sb = ring_u32 + (uint32_t)(slot_of(t) * RSTRIDE * 4);
        const size_t yb = ybase + (size_t)t * CONV_CH;
        if (tid < 32) {
            const int j0 = tid * 4;
            const uint32_t dst = (uint32_t)(((j0 >> 5) * 36 + (j0 & 31)) * 4);
            cp16(sb + dst, g_y + yb + kofs + j0);
        } else if (tid < 64) {
            const int j0 = (tid - 32) * 4;
            const uint32_t dst = (uint32_t)((144 + (j0 >> 5) * 36 + (j0 & 31)) * 4);
            cp16(sb + dst, g_y + yb + qofs + j0);
        } else if (tid < 80) {
            const int i = tid - 64;
            cp16(sb + (uint32_t)((288 + i * 4) * 4), g_y + yb + vofs0 + i * 4);
        } else if (tid < 96) {
            const int i = tid - 80;
            cp16(sb + (uint32_t)((352 + i * 4) * 4),
                 g_proj + pbase + (size_t)t * TOTAL_PROJ + gofs0 + i * 4);
        } else if (tid == 96) {
            cp4(sb + 416 * 4, g_eg + ghofs + t * N_HEADS);
        } else if (tid == 97) {
            cp4(sb + 417 * 4, g_beta + ghofs + t * N_HEADS);
        }
    };

    auto issue_group = [&](int G) {
#pragma unroll
        for (int s = 0; s < GSTEPS; s++) issue_stage(t0 + G * GSTEPS + s);
    };

    issue_group(0);
    asm volatile("cp.async.commit_group;\n" ::: "memory");
    issue_group(1);
    asm volatile("cp.async.commit_group;\n" ::: "memory");

    for (int g = 0; g < NGROUPS_C; g++) {
        asm volatile("cp.async.wait_group 1;\n" ::: "memory");
        __syncthreads();

        if (g + 2 < NGROUPS_C) issue_group(g + 2);
        asm volatile("cp.async.commit_group;\n" ::: "memory");

#pragma unroll
        for (int i = 0; i < GSTEPS; i++) {
            const int t = t0 + g * GSTEPS + i;
            const float* sb = ring + slot_of(t) * RSTRIDE;
            const float eg   = sb[416];
            const float bt   = sb[417];
            const float vv   = sb[288 + col];
            const float gate = sb[352 + col];
            const float4* k4 = (const float4*)(sb + kp * 36);
            const float4* q4 = (const float4*)(sb + 144 + kp * 36);

            float kreg[32];
            float kv0 = 0.f, kv1 = 0.f, kv2 = 0.f, kv3 = 0.f;
#pragma unroll
            for (int u = 0; u < 8; u++) {
                float4 kv4 = k4[u];
                kreg[u * 4 + 0] = kv4.x; kreg[u * 4 + 1] = kv4.y;
                kreg[u * 4 + 2] = kv4.z; kreg[u * 4 + 3] = kv4.w;
                kv0 += kv4.x * S[u * 4 + 0];
                kv1 += kv4.y * S[u * 4 + 1];
                kv2 += kv4.z * S[u * 4 + 2];
                kv3 += kv4.w * S[u * 4 + 3];
            }
            float kv = (kv0 + kv1) + (kv2 + kv3);
            kv += __shfl_xor_sync(0xffffffffu, kv, 1);
            kv += __shfl_xor_sync(0xffffffffu, kv, 2);

            const float delta = (vv - eg * kv) * bt;

            float qs0 = 0.f, qs1 = 0.f, qs2 = 0.f, qs3 = 0.f;
#pragma unroll
            for (int u = 0; u < 8; u++) {
                float4 qv4 = q4[u];
                float s0 = eg * S[u * 4 + 0] + kreg[u * 4 + 0] * delta;
                float s1 = eg * S[u * 4 + 1] + kreg[u * 4 + 1] * delta;
                float s2 = eg * S[u * 4 + 2] + kreg[u * 4 + 2] * delta;
                float s3 = eg * S[u * 4 + 3] + kreg[u * 4 + 3] * delta;
                S[u * 4 + 0] = s0; S[u * 4 + 1] = s1;
                S[u * 4 + 2] = s2; S[u * 4 + 3] = s3;
                qs0 += qv4.x * s0;
                qs1 += qv4.y * s1;
                qs2 += qv4.z * s2;
                qs3 += qv4.w * s3;
            }
            float qs = (qs0 + qs1) + (qs2 + qs3);
            qs += __shfl_xor_sync(0xffffffffu, qs, 1);
            qs += __shfl_xor_sync(0xffffffffu, qs, 2);

            if (kp == 0) {
                const float o  = qs * scale;
                const float sg = gate / (1.f + expf(-gate));
                out[((size_t)(b * L_SEQ + t) * N_HEADS + h) * HEAD_V + vcol] = o * sg;
            }
        }
    }

    // persist state for next chunk
#pragma unroll
    for (int u = 0; u < 8; u++)
        Sg[u] = make_float4(S[u * 4 + 0], S[u * 4 + 1], S[u * 4 + 2], S[u * 4 + 3]);
}

// ---------------------------------------------------------------------------
// Launch: chunked pipeline, recurrence overlapped on a second stream.
// Stream/events are created fresh each call (kernel_launch only runs a few
// times — correctness + capture; the timed loop replays the graph). No static
// state, no caching; identical work every call.
// ---------------------------------------------------------------------------
extern "C" void kernel_launch(void* const* d_in, const int* in_sizes, int n_in,
                              void* d_out, int out_size)
{
    const float* X       = (const float*)d_in[0];
    const float* W       = (const float*)d_in[1];
    const float* Wconv   = (const float*)d_in[2];
    const float* A_log   = (const float*)d_in[3];
    const float* dt_bias = (const float*)d_in[4];
    float* out = (float*)d_out;

    cudaFuncSetAttribute(mma_gemm_kernel,
                         cudaFuncAttributeMaxDynamicSharedMemorySize,
                         SMEM_TOTAL_GEMM);

    cudaStream_t s2;
    cudaStreamCreateWithFlags(&s2, cudaStreamNonBlocking);
    cudaEvent_t evFork[NCHUNK], evJoin;
    for (int i = 0; i < NCHUNK; i++)
        cudaEventCreateWithFlags(&evFork[i], cudaEventDisableTiming);
    cudaEventCreateWithFlags(&evJoin, cudaEventDisableTiming);

    split_kernel<<<2048, 256>>>(X, W);

    for (int c = 0; c < NCHUNK; c++) {
        dim3 gemmGrid(4, (TOTAL_PROJ + 127) / 128);          // (4, 97)
        mma_gemm_kernel<<<gemmGrid, 256, SMEM_TOTAL_GEMM>>>(c);

        scalars_kernel<<<(B_SZ * CL * N_HEADS + 255) / 256, 256>>>(A_log, dt_bias, c);

        dim3 convGrid(CONV_CH / 128, B_SZ * CL / CTILE);     // (64, 64)
        conv_kernel<<<convGrid, 128>>>(Wconv, c);

        cudaEventRecord(evFork[c], 0);
        cudaStreamWaitEvent(s2, evFork[c], 0);
        recurrence_kernel<<<B_SZ * N_HEADS * 4, 256, 0, s2>>>(out, c);
    }

    cudaEventRecord(evJoin, s2);
    cudaStreamWaitEvent(0, evJoin, 0);
    // no destroys: mid-capture destruction can invalidate the captured graph;
    // a handful of leaked handles across the few kernel_launch calls is benign.
}

// round 13
// speedup vs baseline: 1.1014x; 1.1014x over previous
#include <cuda_runtime.h>
#include <cuda_bf16.h>
#include <cstdint>

// ---------------------------------------------------------------------------
// Problem constants
// ---------------------------------------------------------------------------
#define B_SZ     2
#define L_SEQ    2048
#define D_MODEL  2048
#define N_HEADS  16
#define D_HEAD   128
#define HEAD_V   256
#define KEY_DIM  2048
#define VALUE_DIM 4096
#define TOTAL_PROJ 12320
#define CONV_CH  8192
#define BL       (B_SZ * L_SEQ)    // 4096

// ---------------------------------------------------------------------------
// Scratch (static device globals)
// ---------------------------------------------------------------------------
__device__ float g_proj[(size_t)BL * TOTAL_PROJ];
__device__ float g_y[(size_t)BL * CONV_CH];
__device__ float g_eg[BL * N_HEADS];
__device__ float g_beta[BL * N_HEADS];

__device__ __nv_bfloat16 g_Ah[(size_t)BL * D_MODEL];
__device__ __nv_bfloat16 g_Al[(size_t)BL * D_MODEL];
__device__ __nv_bfloat16 g_Bh[(size_t)D_MODEL * TOTAL_PROJ];
__device__ __nv_bfloat16 g_Bl[(size_t)D_MODEL * TOTAL_PROJ];

// ---------------------------------------------------------------------------
// Helpers
// ---------------------------------------------------------------------------
__device__ __forceinline__ uint32_t smem_u32(const void* p) {
    return (uint32_t)__cvta_generic_to_shared(p);
}
__device__ __forceinline__ void ldsm_x4(uint32_t& r0, uint32_t& r1,
                                        uint32_t& r2, uint32_t& r3, uint32_t a) {
    asm volatile("ldmatrix.sync.aligned.m8n8.x4.shared.b16 {%0,%1,%2,%3},[%4];\n"
                 : "=r"(r0), "=r"(r1), "=r"(r2), "=r"(r3) : "r"(a));
}
__device__ __forceinline__ void ldsm_x4_t(uint32_t& r0, uint32_t& r1,
                                          uint32_t& r2, uint32_t& r3, uint32_t a) {
    asm volatile("ldmatrix.sync.aligned.m8n8.x4.trans.shared.b16 {%0,%1,%2,%3},[%4];\n"
                 : "=r"(r0), "=r"(r1), "=r"(r2), "=r"(r3) : "r"(a));
}
__device__ __forceinline__ void mma_bf16(float* c, const uint32_t* a, const uint32_t* b) {
    asm volatile("mma.sync.aligned.m16n8k16.row.col.f32.bf16.bf16.f32 "
                 "{%0,%1,%2,%3},{%4,%5,%6,%7},{%8,%9},{%0,%1,%2,%3};\n"
                 : "+f"(c[0]), "+f"(c[1]), "+f"(c[2]), "+f"(c[3])
                 : "r"(a[0]), "r"(a[1]), "r"(a[2]), "r"(a[3]),
                   "r"(b[0]), "r"(b[1]));
}
__device__ __forceinline__ uint32_t pack_hi2(float x0, float x1) {
    return __byte_perm(__float_as_uint(x0), __float_as_uint(x1), 0x7632);
}
__device__ __forceinline__ uint32_t pack_lo2(float x0, float x1) {
    float h0 = __uint_as_float(__float_as_uint(x0) & 0xffff0000u);
    float h1 = __uint_as_float(__float_as_uint(x1) & 0xffff0000u);
    __nv_bfloat162 l2 = __float22bfloat162_rn(make_float2(x0 - h0, x1 - h1));
    return *reinterpret_cast<uint32_t*>(&l2);
}
__device__ __forceinline__ void cp16(uint32_t dst, const void* src) {
    asm volatile("cp.async.cg.shared.global [%0], [%1], 16;\n" :: "r"(dst), "l"(src));
}
__device__ __forceinline__ void cp4(uint32_t dst, const void* src) {
    asm volatile("cp.async.ca.shared.global [%0], [%1], 4;\n" :: "r"(dst), "l"(src));
}

// ---------------------------------------------------------------------------
// Kernel 0: split fp32 -> bf16 hi/lo for A and B
// ---------------------------------------------------------------------------
#define NA4 ((size_t)BL * D_MODEL / 4)
#define NB4 ((size_t)D_MODEL * TOTAL_PROJ / 4)
__global__ __launch_bounds__(256) void split_kernel(
    const float* __restrict__ A, const float* __restrict__ Bm)
{
    const size_t total = NA4 + NB4;
    for (size_t i = (size_t)blockIdx.x * blockDim.x + threadIdx.x;
         i < total; i += (size_t)gridDim.x * blockDim.x) {
        if (i < NA4) {
            float4 v = ((const float4*)A)[i];
            ((uint2*)g_Ah)[i] = make_uint2(pack_hi2(v.x, v.y), pack_hi2(v.z, v.w));
            ((uint2*)g_Al)[i] = make_uint2(pack_lo2(v.x, v.y), pack_lo2(v.z, v.w));
        } else {
            size_t j = i - NA4;
            float4 v = ((const float4*)Bm)[j];
            ((uint2*)g_Bh)[j] = make_uint2(pack_hi2(v.x, v.y), pack_hi2(v.z, v.w));
            ((uint2*)g_Bl)[j] = make_uint2(pack_lo2(v.x, v.y), pack_lo2(v.z, v.w));
        }
    }
}

// ---------------------------------------------------------------------------
// Kernel 1: GEMM  proj = X[4096,2048] @ W[2048,12320], bf16x3, cp.async x4
// (round-7/10 proven version, unchunked)
// ---------------------------------------------------------------------------
#define STAGES 4
#define AST 24
#define BST 136
#define A_BYTES (128 * AST * 2)
#define B_BYTES (16 * BST * 2)
#define STAGE_BYTES (2 * A_BYTES + 2 * B_BYTES)
#define SMEM_TOTAL_GEMM (STAGES * STAGE_BYTES)

__global__ __launch_bounds__(256) void mma_gemm_kernel()
{
    const int N = TOTAL_PROJ, K = D_MODEL;
    extern __shared__ __align__(16) char smem_raw[];

    const int tid  = threadIdx.x;
    const int lane = tid & 31;
    const int warp = tid >> 5;
    const int wm   = warp & 1;
    const int wn   = warp >> 1;
    const int mrow0 = blockIdx.x * 128;
    const int colBase = blockIdx.y * 128;

    const int ar = tid >> 1;
    const int ac = (tid & 1) << 3;
    const int br = tid >> 4;
    const int bc = (tid & 15) << 3;
    const bool bvalid = (colBase + bc) < N;

    auto sAh = [&](int s) { return (__nv_bfloat16*)(smem_raw + s * STAGE_BYTES); };
    auto sAl = [&](int s) { return (__nv_bfloat16*)(smem_raw + s * STAGE_BYTES + A_BYTES); };
    auto sBh = [&](int s) { return (__nv_bfloat16*)(smem_raw + s * STAGE_BYTES + 2 * A_BYTES); };
    auto sBl = [&](int s) { return (__nv_bfloat16*)(smem_raw + s * STAGE_BYTES + 2 * A_BYTES + B_BYTES); };

    auto copy_stage = [&](int s, int kt) {
        const int k0 = kt * 16;
        cp16(smem_u32(sAh(s) + ar * AST + ac), g_Ah + (size_t)(mrow0 + ar) * K + k0 + ac);
        cp16(smem_u32(sAl(s) + ar * AST + ac), g_Al + (size_t)(mrow0 + ar) * K + k0 + ac);
        if (bvalid) {
            cp16(smem_u32(sBh(s) + br * BST + bc), g_Bh + (size_t)(k0 + br) * N + colBase + bc);
            cp16(smem_u32(sBl(s) + br * BST + bc), g_Bl + (size_t)(k0 + br) * N + colBase + bc);
        } else {
            uint4 z = make_uint4(0, 0, 0, 0);
            *(uint4*)(sBh(s) + br * BST + bc) = z;
            *(uint4*)(sBl(s) + br * BST + bc) = z;
        }
    };

    float acc[4][4][4];
#pragma unroll
    for (int mt = 0; mt < 4; mt++)
#pragma unroll
        for (int nt = 0; nt < 4; nt++)
#pragma unroll
            for (int r = 0; r < 4; r++) acc[mt][nt][r] = 0.f;

    const int KT = K / 16;
#pragma unroll
    for (int s = 0; s < STAGES - 1; s++) {
        copy_stage(s, s);
        asm volatile("cp.async.commit_group;\n" ::: "memory");
    }

    const int m8 = lane >> 3;
    const int j8 = lane & 7;

    for (int kt = 0; kt < KT; kt++) {
        asm volatile("cp.async.wait_group %0;\n" :: "n"(STAGES - 2) : "memory");
        __syncthreads();

        const int nk = kt + STAGES - 1;
        if (nk < KT) copy_stage(nk & (STAGES - 1), nk);
        asm volatile("cp.async.commit_group;\n" ::: "memory");

        const int buf = kt & (STAGES - 1);
        const __nv_bfloat16* Ahs = sAh(buf);
        const __nv_bfloat16* Als = sAl(buf);
        const __nv_bfloat16* Bhs = sBh(buf);
        const __nv_bfloat16* Bls = sBl(buf);

        uint32_t ah[4][4], al[4][4], bh[4][2], bl[4][2];
#pragma unroll
        for (int mt = 0; mt < 4; mt++) {
            const int row = wm * 64 + mt * 16 + (m8 & 1) * 8 + j8;
            const int kc  = (m8 >> 1) * 8;
            ldsm_x4(ah[mt][0], ah[mt][1], ah[mt][2], ah[mt][3],
                    smem_u32(Ahs + row * AST + kc));
            ldsm_x4(al[mt][0], al[mt][1], al[mt][2], al[mt][3],
                    smem_u32(Als + row * AST + kc));
        }
#pragma unroll
        for (int nt2 = 0; nt2 < 2; nt2++) {
            const int kk = (m8 & 1) * 8 + j8;
            const int nn = wn * 32 + nt2 * 16 + (m8 >> 1) * 8;
            uint32_t r0, r1, r2, r3;
            ldsm_x4_t(r0, r1, r2, r3, smem_u32(Bhs + kk * BST + nn));
            bh[nt2 * 2][0] = r0; bh[nt2 * 2][1] = r1;
            bh[nt2 * 2 + 1][0] = r2; bh[nt2 * 2 + 1][1] = r3;
            ldsm_x4_t(r0, r1, r2, r3, smem_u32(Bls + kk * BST + nn));
            bl[nt2 * 2][0] = r0; bl[nt2 * 2][1] = r1;
            bl[nt2 * 2 + 1][0] = r2; bl[nt2 * 2 + 1][1] = r3;
        }

#pragma unroll
        for (int mt = 0; mt < 4; mt++)
#pragma unroll
            for (int nt = 0; nt < 4; nt++) {
                mma_bf16(acc[mt][nt], al[mt], bh[nt]);
                mma_bf16(acc[mt][nt], ah[mt], bl[nt]);
                mma_bf16(acc[mt][nt], ah[mt], bh[nt]);
            }
        __syncthreads();
    }

    const int g4 = lane >> 2;
    const int tg = lane & 3;
#pragma unroll
    for (int mt = 0; mt < 4; mt++) {
        const int row0 = mrow0 + wm * 64 + mt * 16 + g4;
        float* C0 = g_proj + (size_t)row0 * N;
        float* C1 = g_proj + (size_t)(row0 + 8) * N;
#pragma unroll
        for (int nt = 0; nt < 4; nt++) {
            const int col = colBase + wn * 32 + nt * 8 + tg * 2;
            if (col < N) {
                *(float2*)(C0 + col) = make_float2(acc[mt][nt][0], acc[mt][nt][1]);
                *(float2*)(C1 + col) = make_float2(acc[mt][nt][2], acc[mt][nt][3]);
            }
        }
    }
}

// ---------------------------------------------------------------------------
// Kernel 2: per-(b,l,h) scalars
// ---------------------------------------------------------------------------
__global__ void scalars_kernel(const float* __restrict__ A_log,
                               const float* __restrict__ dt_bias)
{
    int i = blockIdx.x * blockDim.x + threadIdx.x;
    if (i >= BL * N_HEADS) return;
    int bl = i >> 4;
    int h  = i & 15;
    const float* row = g_proj + (size_t)bl * TOTAL_PROJ;
    float bv = row[12288 + h];
    g_beta[i] = 1.f / (1.f + expf(-bv));
    float a = row[12304 + h] + dt_bias[h];
    float sp = (a > 15.f) ? a : log1pf(expf(a));
    float g = -expf(A_log[h]) * sp;
    g_eg[i] = expf(g);
}

// ---------------------------------------------------------------------------
// Kernel 3: depthwise causal conv(4) + SiLU + per-head L2 norm (q,k only)
// ---------------------------------------------------------------------------
#define CTILE 8
__global__ __launch_bounds__(128) void conv_kernel(const float* __restrict__ Wconv)
{
    const int grp  = blockIdx.x;
    const int tile = blockIdx.y;
    const int b    = tile / (L_SEQ / CTILE);
    const int l0   = (tile % (L_SEQ / CTILE)) * CTILE;
    const int c    = grp * 128 + threadIdx.x;
    const int lane = threadIdx.x & 31;
    const int wid  = threadIdx.x >> 5;

    const float* w = Wconv + c * 4;
    const float w0 = w[0], w1 = w[1], w2 = w[2], w3 = w[3];

    const float* pbase = g_proj + ((size_t)(b * L_SEQ + l0)) * TOTAL_PROJ + c;
    float xv[CTILE + 3];
#pragma unroll
    for (int j = 0; j < CTILE + 3; j++) {
        const int l = l0 - 3 + j;
        xv[j] = (l >= 0) ? pbase[(ptrdiff_t)(j - 3) * TOTAL_PROJ] : 0.f;
    }

    __shared__ float red[4];
    float* yrow = g_y + ((size_t)(b * L_SEQ + l0)) * CONV_CH + c;

#pragma unroll
    for (int t = 0; t < CTILE; t++) {
        float acc = xv[t] * w0 + xv[t + 1] * w1 + xv[t + 2] * w2 + xv[t + 3] * w3;
        float s = acc / (1.f + expf(-acc));
        float val = s;
        if (grp < 32) {
            float ss = s * s;
#pragma unroll
            for (int off = 16; off > 0; off >>= 1)
                ss += __shfl_xor_sync(0xffffffffu, ss, off);
            if (lane == 0) red[wid] = ss;
            __syncthreads();
            float tot = red[0] + red[1] + red[2] + red[3];
            val = s * rsqrtf(tot + 1e-6f);
            __syncthreads();
        }
        yrow[(size_t)t * CONV_CH] = val;
    }
}

// ---------------------------------------------------------------------------
// Kernel 4: gated delta-rule recurrence.
// 256 CTAs = (b,h) x 8 v-slices of 32 cols; 256 threads:
//   col = tid>>3 (0..31), kp = tid&7 (16 S-rows each).
// 3-group x 4-step cp.async ring, one wait+barrier per 4 steps.
// Ring stage layout (floats), stride 388:
//   k  in 8 blocks of 20 (16 data + 4 pad): word (j>>4)*20 + (j&15)
//   q  at 160 + same; v [320..351]; gate [352..383]; eg [384]; beta [385]
// ---------------------------------------------------------------------------
#define RGROUPS 3
#define GSTEPS  4
#define RSTAGES (RGROUPS * GSTEPS)
#define RSTRIDE 388
#define NGROUPS (L_SEQ / GSTEPS)

__global__ __launch_bounds__(256, 1) void recurrence_kernel(float* __restrict__ out)
{
    const int slice = blockIdx.x & 7;
    const int bh    = blockIdx.x >> 3;
    const int b     = bh >> 4;
    const int h     = bh & 15;
    const int tid   = threadIdx.x;
    const int col   = tid >> 3;       // 0..31
    const int kp    = tid & 7;        // 0..7
    const int vcol  = slice * 32 + col;

    __shared__ __align__(16) float ring[RSTAGES * RSTRIDE];

    float S[16];
#pragma unroll
    for (int j = 0; j < 16; j++) S[j] = 0.f;

    const float scale = 0.08838834764831845f;   // 128^-0.5

    const size_t ybase = (size_t)b * L_SEQ * CONV_CH;
    const size_t pbase = (size_t)b * L_SEQ * TOTAL_PROJ;
    const int qofs  = h * 128;
    const int kofs  = KEY_DIM + h * 128;
    const int vofs0 = 2 * KEY_DIM + h * 256 + slice * 32;
    const int gofs0 = 2 * KEY_DIM + VALUE_DIM + h * 256 + slice * 32;
    const int ghofs = (b * L_SEQ) * N_HEADS + h;

    const uint32_t ring_u32 = smem_u32(ring);

    auto slot_of = [&](int t) -> int {
        return ((t >> 2) % RGROUPS) * GSTEPS + (t & 3);
    };

    auto issue_stage = [&](int t) {
        const uint32_t sb = ring_u32 + (uint32_t)(slot_of(t) * RSTRIDE * 4);
        const size_t yb = ybase + (size_t)t * CONV_CH;
        if (tid < 32) {
            const int j0 = tid * 4;                                   // k rows
            const uint32_t dst = (uint32_t)((((j0 >> 4) * 20) + (j0 & 15)) * 4);
            cp16(sb + dst, g_y + yb + kofs + j0);
        } else if (tid < 64) {
            const int j0 = (tid - 32) * 4;                            // q rows
            const uint32_t dst = (uint32_t)((160 + ((j0 >> 4) * 20) + (j0 & 15)) * 4);
            cp16(sb + dst, g_y + yb + qofs + j0);
        } else if (tid < 72) {
            const int i = tid - 64;                                   // v (32)
            cp16(sb + (uint32_t)((320 + i * 4) * 4), g_y + yb + vofs0 + i * 4);
        } else if (tid < 80) {
            const int i = tid - 72;                                   // gate (32)
            cp16(sb + (uint32_t)((352 + i * 4) * 4),
                 g_proj + pbase + (size_t)t * TOTAL_PROJ + gofs0 + i * 4);
        } else if (tid == 80) {
            cp4(sb + 384 * 4, g_eg + ghofs + t * N_HEADS);
        } else if (tid == 81) {
            cp4(sb + 385 * 4, g_beta + ghofs + t * N_HEADS);
        }
    };

    auto issue_group = [&](int G) {
#pragma unroll
        for (int s = 0; s < GSTEPS; s++) issue_stage(G * GSTEPS + s);
    };

    issue_group(0);
    asm volatile("cp.async.commit_group;\n" ::: "memory");
    issue_group(1);
    asm volatile("cp.async.commit_group;\n" ::: "memory");

    for (int g = 0; g < NGROUPS; g++) {
        asm volatile("cp.async.wait_group 1;\n" ::: "memory");
        __syncthreads();

        if (g + 2 < NGROUPS) issue_group(g + 2);
        asm volatile("cp.async.commit_group;\n" ::: "memory");

#pragma unroll
        for (int i = 0; i < GSTEPS; i++) {
            const int t = g * GSTEPS + i;
            const float* sb = ring + slot_of(t) * RSTRIDE;
            const float eg   = sb[384];
            const float bt   = sb[385];
            const float vv   = sb[320 + col];
            const float gate = sb[352 + col];
            const float4* k4 = (const float4*)(sb + kp * 20);
            const float4* q4 = (const float4*)(sb + 160 + kp * 20);

            // pass 1: kv = k . S_old (k kept in regs)
            float kreg[16];
            float kv0 = 0.f, kv1 = 0.f, kv2 = 0.f, kv3 = 0.f;
#pragma unroll
            for (int u = 0; u < 4; u++) {
                float4 kv4 = k4[u];
                kreg[u * 4 + 0] = kv4.x; kreg[u * 4 + 1] = kv4.y;
                kreg[u * 4 + 2] = kv4.z; kreg[u * 4 + 3] = kv4.w;
                kv0 += kv4.x * S[u * 4 + 0];
                kv1 += kv4.y * S[u * 4 + 1];
                kv2 += kv4.z * S[u * 4 + 2];
                kv3 += kv4.w * S[u * 4 + 3];
            }
            float kv = (kv0 + kv1) + (kv2 + kv3);
            kv += __shfl_xor_sync(0xffffffffu, kv, 1);
            kv += __shfl_xor_sync(0xffffffffu, kv, 2);
            kv += __shfl_xor_sync(0xffffffffu, kv, 4);

            const float delta = (vv - eg * kv) * bt;

            // pass 2: S = eg*S + k*delta, fused with qs = q . S_new
            float qs0 = 0.f, qs1 = 0.f, qs2 = 0.f, qs3 = 0.f;
#pragma unroll
            for (int u = 0; u < 4; u++) {
                float4 qv4 = q4[u];
                float s0 = eg * S[u * 4 + 0] + kreg[u * 4 + 0] * delta;
                float s1 = eg * S[u * 4 + 1] + kreg[u * 4 + 1] * delta;
                float s2 = eg * S[u * 4 + 2] + kreg[u * 4 + 2] * delta;
                float s3 = eg * S[u * 4 + 3] + kreg[u * 4 + 3] * delta;
                S[u * 4 + 0] = s0; S[u * 4 + 1] = s1;
                S[u * 4 + 2] = s2; S[u * 4 + 3] = s3;
                qs0 += qv4.x * s0;
                qs1 += qv4.y * s1;
                qs2 += qv4.z * s2;
                qs3 += qv4.w * s3;
            }
            float qs = (qs0 + qs1) + (qs2 + qs3);
            qs += __shfl_xor_sync(0xffffffffu, qs, 1);
            qs += __shfl_xor_sync(0xffffffffu, qs, 2);
            qs += __shfl_xor_sync(0xffffffffu, qs, 4);

            if (kp == 0) {
                const float o  = qs * scale;
                const float sg = gate / (1.f + expf(-gate));
                out[((size_t)(b * L_SEQ + t) * N_HEADS + h) * HEAD_V + vcol] = o * sg;
            }
        }
    }
}

// ---------------------------------------------------------------------------
// Launch (single stream)
// ---------------------------------------------------------------------------
extern "C" void kernel_launch(void* const* d_in, const int* in_sizes, int n_in,
                              void* d_out, int out_size)
{
    const float* X       = (const float*)d_in[0];
    const float* W       = (const float*)d_in[1];
    const float* Wconv   = (const float*)d_in[2];
    const float* A_log   = (const float*)d_in[3];
    const float* dt_bias = (const float*)d_in[4];
    float* out = (float*)d_out;

    cudaFuncSetAttribute(mma_gemm_kernel,
                         cudaFuncAttributeMaxDynamicSharedMemorySize,
                         SMEM_TOTAL_GEMM);

    split_kernel<<<2048, 256>>>(X, W);

    dim3 gemmGrid(BL / 128, (TOTAL_PROJ + 127) / 128);   // (32, 97)
    mma_gemm_kernel<<<gemmGrid, 256, SMEM_TOTAL_GEMM>>>();

    scalars_kernel<<<(BL * N_HEADS + 255) / 256, 256>>>(A_log, dt_bias);

    dim3 convGrid(CONV_CH / 128, BL / CTILE);
    conv_kernel<<<convGrid, 128>>>(Wconv);

    recurrence_kernel<<<B_SZ * N_HEADS * 8, 256>>>(out);
}

// round 15
// speedup vs baseline: 1.1698x; 1.0622x over previous
#include <cuda_runtime.h>
#include <cuda_bf16.h>
#include <cstdint>

// ---------------------------------------------------------------------------
// Problem constants
// ---------------------------------------------------------------------------
#define B_SZ     2
#define L_SEQ    2048
#define D_MODEL  2048
#define N_HEADS  16
#define D_HEAD   128
#define HEAD_V   256
#define KEY_DIM  2048
#define VALUE_DIM 4096
#define TOTAL_PROJ 12320
#define CONV_CH  8192
#define BL       (B_SZ * L_SEQ)    // 4096

// ---------------------------------------------------------------------------
// Scratch (static device globals)
// ---------------------------------------------------------------------------
__device__ float g_proj[(size_t)BL * TOTAL_PROJ];
__device__ float g_y[(size_t)BL * CONV_CH];
__device__ float g_eg[BL * N_HEADS];
__device__ float g_beta[BL * N_HEADS];
__device__ float g_mnq[32 * L_SEQ * 3 + 4];   // per (b,h,t): k.kprev, q.kprev, q.k

__device__ __nv_bfloat16 g_Ah[(size_t)BL * D_MODEL];
__device__ __nv_bfloat16 g_Al[(size_t)BL * D_MODEL];
__device__ __nv_bfloat16 g_Bh[(size_t)D_MODEL * TOTAL_PROJ];
__device__ __nv_bfloat16 g_Bl[(size_t)D_MODEL * TOTAL_PROJ];

// ---------------------------------------------------------------------------
// Helpers
// ---------------------------------------------------------------------------
__device__ __forceinline__ uint32_t smem_u32(const void* p) {
    return (uint32_t)__cvta_generic_to_shared(p);
}
__device__ __forceinline__ void ldsm_x4(uint32_t& r0, uint32_t& r1,
                                        uint32_t& r2, uint32_t& r3, uint32_t a) {
    asm volatile("ldmatrix.sync.aligned.m8n8.x4.shared.b16 {%0,%1,%2,%3},[%4];\n"
                 : "=r"(r0), "=r"(r1), "=r"(r2), "=r"(r3) : "r"(a));
}
__device__ __forceinline__ void ldsm_x4_t(uint32_t& r0, uint32_t& r1,
                                          uint32_t& r2, uint32_t& r3, uint32_t a) {
    asm volatile("ldmatrix.sync.aligned.m8n8.x4.trans.shared.b16 {%0,%1,%2,%3},[%4];\n"
                 : "=r"(r0), "=r"(r1), "=r"(r2), "=r"(r3) : "r"(a));
}
__device__ __forceinline__ void mma_bf16(float* c, const uint32_t* a, const uint32_t* b) {
    asm volatile("mma.sync.aligned.m16n8k16.row.col.f32.bf16.bf16.f32 "
                 "{%0,%1,%2,%3},{%4,%5,%6,%7},{%8,%9},{%0,%1,%2,%3};\n"
                 : "+f"(c[0]), "+f"(c[1]), "+f"(c[2]), "+f"(c[3])
                 : "r"(a[0]), "r"(a[1]), "r"(a[2]), "r"(a[3]),
                   "r"(b[0]), "r"(b[1]));
}
__device__ __forceinline__ uint32_t pack_hi2(float x0, float x1) {
    return __byte_perm(__float_as_uint(x0), __float_as_uint(x1), 0x7632);
}
__device__ __forceinline__ uint32_t pack_lo2(float x0, float x1) {
    float h0 = __uint_as_float(__float_as_uint(x0) & 0xffff0000u);
    float h1 = __uint_as_float(__float_as_uint(x1) & 0xffff0000u);
    __nv_bfloat162 l2 = __float22bfloat162_rn(make_float2(x0 - h0, x1 - h1));
    return *reinterpret_cast<uint32_t*>(&l2);
}
__device__ __forceinline__ void cp16(uint32_t dst, const void* src) {
    asm volatile("cp.async.cg.shared.global [%0], [%1], 16;\n" :: "r"(dst), "l"(src));
}
__device__ __forceinline__ void cp4(uint32_t dst, const void* src) {
    asm volatile("cp.async.ca.shared.global [%0], [%1], 4;\n" :: "r"(dst), "l"(src));
}

// ---------------------------------------------------------------------------
// Kernel 0: split fp32 -> bf16 hi/lo for A and B
// ---------------------------------------------------------------------------
#define NA4 ((size_t)BL * D_MODEL / 4)
#define NB4 ((size_t)D_MODEL * TOTAL_PROJ / 4)
__global__ __launch_bounds__(256) void split_kernel(
    const float* __restrict__ A, const float* __restrict__ Bm)
{
    const size_t total = NA4 + NB4;
    for (size_t i = (size_t)blockIdx.x * blockDim.x + threadIdx.x;
         i < total; i += (size_t)gridDim.x * blockDim.x) {
        if (i < NA4) {
            float4 v = ((const float4*)A)[i];
            ((uint2*)g_Ah)[i] = make_uint2(pack_hi2(v.x, v.y), pack_hi2(v.z, v.w));
            ((uint2*)g_Al)[i] = make_uint2(pack_lo2(v.x, v.y), pack_lo2(v.z, v.w));
        } else {
            size_t j = i - NA4;
            float4 v = ((const float4*)Bm)[j];
            ((uint2*)g_Bh)[j] = make_uint2(pack_hi2(v.x, v.y), pack_hi2(v.z, v.w));
            ((uint2*)g_Bl)[j] = make_uint2(pack_lo2(v.x, v.y), pack_lo2(v.z, v.w));
        }
    }
}

// ---------------------------------------------------------------------------
// Kernel 1: GEMM  proj = X[4096,2048] @ W[2048,12320], bf16x3, cp.async x4
// ---------------------------------------------------------------------------
#define STAGES 4
#define AST 24
#define BST 136
#define A_BYTES (128 * AST * 2)
#define B_BYTES (16 * BST * 2)
#define STAGE_BYTES (2 * A_BYTES + 2 * B_BYTES)
#define SMEM_TOTAL_GEMM (STAGES * STAGE_BYTES)

__global__ __launch_bounds__(256) void mma_gemm_kernel()
{
    const int N = TOTAL_PROJ, K = D_MODEL;
    extern __shared__ __align__(16) char smem_raw[];

    const int tid  = threadIdx.x;
    const int lane = tid & 31;
    const int warp = tid >> 5;
    const int wm   = warp & 1;
    const int wn   = warp >> 1;
    const int mrow0 = blockIdx.x * 128;
    const int colBase = blockIdx.y * 128;

    const int ar = tid >> 1;
    const int ac = (tid & 1) << 3;
    const int br = tid >> 4;
    const int bc = (tid & 15) << 3;
    const bool bvalid = (colBase + bc) < N;

    auto sAh = [&](int s) { return (__nv_bfloat16*)(smem_raw + s * STAGE_BYTES); };
    auto sAl = [&](int s) { return (__nv_bfloat16*)(smem_raw + s * STAGE_BYTES + A_BYTES); };
    auto sBh = [&](int s) { return (__nv_bfloat16*)(smem_raw + s * STAGE_BYTES + 2 * A_BYTES); };
    auto sBl = [&](int s) { return (__nv_bfloat16*)(smem_raw + s * STAGE_BYTES + 2 * A_BYTES + B_BYTES); };

    auto copy_stage = [&](int s, int kt) {
        const int k0 = kt * 16;
        cp16(smem_u32(sAh(s) + ar * AST + ac), g_Ah + (size_t)(mrow0 + ar) * K + k0 + ac);
        cp16(smem_u32(sAl(s) + ar * AST + ac), g_Al + (size_t)(mrow0 + ar) * K + k0 + ac);
        if (bvalid) {
            cp16(smem_u32(sBh(s) + br * BST + bc), g_Bh + (size_t)(k0 + br) * N + colBase + bc);
            cp16(smem_u32(sBl(s) + br * BST + bc), g_Bl + (size_t)(k0 + br) * N + colBase + bc);
        } else {
            uint4 z = make_uint4(0, 0, 0, 0);
            *(uint4*)(sBh(s) + br * BST + bc) = z;
            *(uint4*)(sBl(s) + br * BST + bc) = z;
        }
    };

    float acc[4][4][4];
#pragma unroll
    for (int mt = 0; mt < 4; mt++)
#pragma unroll
        for (int nt = 0; nt < 4; nt++)
#pragma unroll
            for (int r = 0; r < 4; r++) acc[mt][nt][r] = 0.f;

    const int KT = K / 16;
#pragma unroll
    for (int s = 0; s < STAGES - 1; s++) {
        copy_stage(s, s);
        asm volatile("cp.async.commit_group;\n" ::: "memory");
    }

    const int m8 = lane >> 3;
    const int j8 = lane & 7;

    for (int kt = 0; kt < KT; kt++) {
        asm volatile("cp.async.wait_group %0;\n" :: "n"(STAGES - 2) : "memory");
        __syncthreads();

        const int nk = kt + STAGES - 1;
        if (nk < KT) copy_stage(nk & (STAGES - 1), nk);
        asm volatile("cp.async.commit_group;\n" ::: "memory");

        const int buf = kt & (STAGES - 1);
        const __nv_bfloat16* Ahs = sAh(buf);
        const __nv_bfloat16* Als = sAl(buf);
        const __nv_bfloat16* Bhs = sBh(buf);
        const __nv_bfloat16* Bls = sBl(buf);

        uint32_t ah[4][4], al[4][4], bh[4][2], bl[4][2];
#pragma unroll
        for (int mt = 0; mt < 4; mt++) {
            const int row = wm * 64 + mt * 16 + (m8 & 1) * 8 + j8;
            const int kc  = (m8 >> 1) * 8;
            ldsm_x4(ah[mt][0], ah[mt][1], ah[mt][2], ah[mt][3],
                    smem_u32(Ahs + row * AST + kc));
            ldsm_x4(al[mt][0], al[mt][1], al[mt][2], al[mt][3],
                    smem_u32(Als + row * AST + kc));
        }
#pragma unroll
        for (int nt2 = 0; nt2 < 2; nt2++) {
            const int kk = (m8 & 1) * 8 + j8;
            const int nn = wn * 32 + nt2 * 16 + (m8 >> 1) * 8;
            uint32_t r0, r1, r2, r3;
            ldsm_x4_t(r0, r1, r2, r3, smem_u32(Bhs + kk * BST + nn));
            bh[nt2 * 2][0] = r0; bh[nt2 * 2][1] = r1;
            bh[nt2 * 2 + 1][0] = r2; bh[nt2 * 2 + 1][1] = r3;
            ldsm_x4_t(r0, r1, r2, r3, smem_u32(Bls + kk * BST + nn));
            bl[nt2 * 2][0] = r0; bl[nt2 * 2][1] = r1;
            bl[nt2 * 2 + 1][0] = r2; bl[nt2 * 2 + 1][1] = r3;
        }

#pragma unroll
        for (int mt = 0; mt < 4; mt++)
#pragma unroll
            for (int nt = 0; nt < 4; nt++) {
                mma_bf16(acc[mt][nt], al[mt], bh[nt]);
                mma_bf16(acc[mt][nt], ah[mt], bl[nt]);
                mma_bf16(acc[mt][nt], ah[mt], bh[nt]);
            }
        __syncthreads();
    }

    const int g4 = lane >> 2;
    const int tg = lane & 3;
#pragma unroll
    for (int mt = 0; mt < 4; mt++) {
        const int row0 = mrow0 + wm * 64 + mt * 16 + g4;
        float* C0 = g_proj + (size_t)row0 * N;
        float* C1 = g_proj + (size_t)(row0 + 8) * N;
#pragma unroll
        for (int nt = 0; nt < 4; nt++) {
            const int col = colBase + wn * 32 + nt * 8 + tg * 2;
            if (col < N) {
                *(float2*)(C0 + col) = make_float2(acc[mt][nt][0], acc[mt][nt][1]);
                *(float2*)(C1 + col) = make_float2(acc[mt][nt][2], acc[mt][nt][3]);
            }
        }
    }
}

// ---------------------------------------------------------------------------
// Kernel 2: per-(b,l,h) scalars
// ---------------------------------------------------------------------------
__global__ void scalars_kernel(const float* __restrict__ A_log,
                               const float* __restrict__ dt_bias)
{
    int i = blockIdx.x * blockDim.x + threadIdx.x;
    if (i >= BL * N_HEADS) return;
    int bl = i >> 4;
    int h  = i & 15;
    const float* row = g_proj + (size_t)bl * TOTAL_PROJ;
    float bv = row[12288 + h];
    g_beta[i] = 1.f / (1.f + expf(-bv));
    float a = row[12304 + h] + dt_bias[h];
    float sp = (a > 15.f) ? a : log1pf(expf(a));
    float g = -expf(A_log[h]) * sp;
    g_eg[i] = expf(g);
}

// ---------------------------------------------------------------------------
// Kernel 3: depthwise causal conv(4) + SiLU + per-head L2 norm (q,k only)
// ---------------------------------------------------------------------------
#define CTILE 8
__global__ __launch_bounds__(128) void conv_kernel(const float* __restrict__ Wconv)
{
    const int grp  = blockIdx.x;
    const int tile = blockIdx.y;
    const int b    = tile / (L_SEQ / CTILE);
    const int l0   = (tile % (L_SEQ / CTILE)) * CTILE;
    const int c    = grp * 128 + threadIdx.x;
    const int lane = threadIdx.x & 31;
    const int wid  = threadIdx.x >> 5;

    const float* w = Wconv + c * 4;
    const float w0 = w[0], w1 = w[1], w2 = w[2], w3 = w[3];

    const float* pbase = g_proj + ((size_t)(b * L_SEQ + l0)) * TOTAL_PROJ + c;
    float xv[CTILE + 3];
#pragma unroll
    for (int j = 0; j < CTILE + 3; j++) {
        const int l = l0 - 3 + j;
        xv[j] = (l >= 0) ? pbase[(ptrdiff_t)(j - 3) * TOTAL_PROJ] : 0.f;
    }

    __shared__ float red[4];
    float* yrow = g_y + ((size_t)(b * L_SEQ + l0)) * CONV_CH + c;

#pragma unroll
    for (int t = 0; t < CTILE; t++) {
        float acc = xv[t] * w0 + xv[t + 1] * w1 + xv[t + 2] * w2 + xv[t + 3] * w3;
        float s = acc / (1.f + expf(-acc));
        float val = s;
        if (grp < 32) {
            float ss = s * s;
#pragma unroll
            for (int off = 16; off > 0; off >>= 1)
                ss += __shfl_xor_sync(0xffffffffu, ss, off);
            if (lane == 0) red[wid] = ss;
            __syncthreads();
            float tot = red[0] + red[1] + red[2] + red[3];
            val = s * rsqrtf(tot + 1e-6f);
            __syncthreads();
        }
        yrow[(size_t)t * CONV_CH] = val;
    }
}

// ---------------------------------------------------------------------------
// Kernel 3b: per-(b,h,t) scalar dots: m = k_t.k_{t-1}, n1 = q_t.k_{t-1},
// n0 = q_t.k_t  (warp per (bh,t); lane handles 4 dims)
// ---------------------------------------------------------------------------
__global__ __launch_bounds__(256) void mnq_kernel()
{
    const int gw   = blockIdx.x * 8 + (threadIdx.x >> 5);   // 0..65535
    const int lane = threadIdx.x & 31;
    const int bh = gw >> 11;          // 0..31
    const int t  = gw & 2047;
    const int b  = bh >> 4;
    const int h  = bh & 15;

    const float* base = g_y + (size_t)(b * L_SEQ + t) * CONV_CH;
    float4 kt = ((const float4*)(base + KEY_DIM + h * 128))[lane];
    float4 qt = ((const float4*)(base + h * 128))[lane];
    float4 kp = make_float4(0.f, 0.f, 0.f, 0.f);
    if (t > 0)
        kp = ((const float4*)(base - CONV_CH + KEY_DIM + h * 128))[lane];

    float m  = kt.x * kp.x + kt.y * kp.y + kt.z * kp.z + kt.w * kp.w;
    float n1 = qt.x * kp.x + qt.y * kp.y + qt.z * kp.z + qt.w * kp.w;
    float n0 = qt.x * kt.x + qt.y * kt.y + qt.z * kt.z + qt.w * kt.w;
#pragma unroll
    for (int off = 16; off > 0; off >>= 1) {
        m  += __shfl_xor_sync(0xffffffffu, m,  off);
        n1 += __shfl_xor_sync(0xffffffffu, n1, off);
        n0 += __shfl_xor_sync(0xffffffffu, n0, off);
    }
    if (lane == 0) {
        float* o = g_mnq + (size_t)(bh * L_SEQ + t) * 3;
        o[0] = m; o[1] = n1; o[2] = n0;
    }
}

// ---------------------------------------------------------------------------
// Kernel 4: gated delta-rule recurrence, 2-step lookahead form.
// 128 CTAs = (b,h) x 4 v-slices of 64 cols; 256 threads (col=tid>>2, kp=tid&3).
// NOTE: wait_group 0 (not 1) — the lookahead reads stage t+1, which at the
// last step of a group lies in the NEXT group; all issued groups must be
// complete before the inner loop.
// ---------------------------------------------------------------------------
#define RGROUPS 3
#define GSTEPS  4
#define RSTAGES (RGROUPS * GSTEPS)
#define RSTRIDE 424
#define NGROUPS (L_SEQ / GSTEPS)

__global__ __launch_bounds__(256, 1) void recurrence_kernel(float* __restrict__ out)
{
    const int slice = blockIdx.x & 3;
    const int bh    = blockIdx.x >> 2;
    const int b     = bh >> 4;
    const int h     = bh & 15;
    const int tid   = threadIdx.x;
    const int col   = tid >> 2;
    const int kp    = tid & 3;
    const int vcol  = slice * 64 + col;

    __shared__ __align__(16) float ring[RSTAGES * RSTRIDE];

    float S[32];
#pragma unroll
    for (int j = 0; j < 32; j++) S[j] = 0.f;
    float kb0[32], kb1[32];

    const float scale = 0.08838834764831845f;   // 128^-0.5

    const size_t ybase = (size_t)b * L_SEQ * CONV_CH;
    const size_t pbase = (size_t)b * L_SEQ * TOTAL_PROJ;
    const int qofs  = h * 128;
    const int kofs  = KEY_DIM + h * 128;
    const int vofs0 = 2 * KEY_DIM + h * 256 + slice * 64;
    const int gofs0 = 2 * KEY_DIM + VALUE_DIM + h * 256 + slice * 64;
    const int ghofs = (b * L_SEQ) * N_HEADS + h;
    const float* mnq_base = g_mnq + (size_t)bh * L_SEQ * 3;

    const uint32_t ring_u32 = smem_u32(ring);

    auto slot_of = [&](int t) -> int {
        return ((t >> 2) % RGROUPS) * GSTEPS + (t & 3);
    };

    auto issue_stage = [&](int t) {
        const uint32_t sb = ring_u32 + (uint32_t)(slot_of(t) * RSTRIDE * 4);
        const size_t yb = ybase + (size_t)t * CONV_CH;
        if (tid < 32) {
            const int j0 = tid * 4;
            const uint32_t dst = (uint32_t)(((j0 >> 5) * 36 + (j0 & 31)) * 4);
            cp16(sb + dst, g_y + yb + kofs + j0);
        } else if (tid < 64) {
            const int j0 = (tid - 32) * 4;
            const uint32_t dst = (uint32_t)((144 + (j0 >> 5) * 36 + (j0 & 31)) * 4);
            cp16(sb + dst, g_y + yb + qofs + j0);
        } else if (tid < 80) {
            const int i = tid - 64;
            cp16(sb + (uint32_t)((288 + i * 4) * 4), g_y + yb + vofs0 + i * 4);
        } else if (tid < 96) {
            const int i = tid - 80;
            cp16(sb + (uint32_t)((352 + i * 4) * 4),
                 g_proj + pbase + (size_t)t * TOTAL_PROJ + gofs0 + i * 4);
        } else if (tid == 96) {
            cp4(sb + 416 * 4, g_eg + ghofs + t * N_HEADS);
        } else if (tid == 97) {
            cp4(sb + 417 * 4, g_beta + ghofs + t * N_HEADS);
        } else if (tid < 101) {
            const int i = tid - 98;
            cp4(sb + (uint32_t)((418 + i) * 4), mnq_base + t * 3 + i);
        }
    };

    auto issue_group = [&](int G) {
#pragma unroll
        for (int s = 0; s < GSTEPS; s++) issue_stage(G * GSTEPS + s);
    };

    issue_group(0);
    asm volatile("cp.async.commit_group;\n" ::: "memory");
    issue_group(1);
    asm volatile("cp.async.commit_group;\n" ::: "memory");

    // carried lookahead state
    float cred = 0.f, dred = 0.f;     // c_t = k_t.S_{t-2}, d_t = q_t.S_{t-2}
    float dprev = 0.f, egprev = 0.f;  // delta_{t-1}, eg_{t-1}

    for (int g = 0; g < NGROUPS; g++) {
        asm volatile("cp.async.wait_group 0;\n" ::: "memory");
        __syncthreads();

        if (g + 2 < NGROUPS) issue_group(g + 2);
        asm volatile("cp.async.commit_group;\n" ::: "memory");

#pragma unroll
        for (int i = 0; i < GSTEPS; i++) {
            const int t = g * GSTEPS + i;
            const float* sb = ring + slot_of(t) * RSTRIDE;

            // kcur = k_t (loaded as "knext" last iteration; bootstrap at t=0)
            float* kcur = (i & 1) ? kb1 : kb0;
            float* knxt = (i & 1) ? kb0 : kb1;
            if (g == 0 && i == 0) {
                const float4* k4 = (const float4*)(sb + kp * 36);
#pragma unroll
                for (int u = 0; u < 8; u++) {
                    float4 kv4 = k4[u];
                    kcur[u * 4 + 0] = kv4.x; kcur[u * 4 + 1] = kv4.y;
                    kcur[u * 4 + 2] = kv4.z; kcur[u * 4 + 3] = kv4.w;
                }
            }

            const float eg   = sb[416];
            const float bt   = sb[417];
            const float m    = sb[418];
            const float n1   = sb[419];
            const float n0   = sb[420];
            const float vv   = sb[288 + col];
            const float gate = sb[352 + col];

            // serial chain (exact algebra):
            // kv_t = eg_{t-1} * (k_t.S_{t-2}) + (k_t.k_{t-1}) * delta_{t-1}
            const float kv    = egprev * cred + m * dprev;
            const float delta = bt * (vv - eg * kv);
            // o_t = scale*( eg_t*(eg_{t-1}*(q_t.S_{t-2}) + (q_t.k_{t-1})*d_{t-1})
            //              + (q_t.k_t)*delta_t )
            const float qS1 = egprev * dred + n1 * dprev;
            const float o   = scale * (eg * qS1 + n0 * delta);
            if (kp == 0) {
                const float sg = gate / (1.f + expf(-gate));
                out[((size_t)(b * L_SEQ + t) * N_HEADS + h) * HEAD_V + vcol] = o * sg;
            }

            // lookahead: load k_{t+1}, q_{t+1}; dot against S (== S_{t-1}, pre-update)
            const float* sbn = ring + slot_of(t + 1) * RSTRIDE;
            const float4* kn4 = (const float4*)(sbn + kp * 36);
            const float4* qn4 = (const float4*)(sbn + 144 + kp * 36);
            float c0 = 0.f, c1 = 0.f, c2 = 0.f, c3 = 0.f;
            float d0 = 0.f, d1 = 0.f, d2 = 0.f, d3 = 0.f;
#pragma unroll
            for (int u = 0; u < 8; u++) {
                float4 kv4 = kn4[u];
                float4 qv4 = qn4[u];
                knxt[u * 4 + 0] = kv4.x; knxt[u * 4 + 1] = kv4.y;
                knxt[u * 4 + 2] = kv4.z; knxt[u * 4 + 3] = kv4.w;
                c0 += kv4.x * S[u * 4 + 0];
                c1 += kv4.y * S[u * 4 + 1];
                c2 += kv4.z * S[u * 4 + 2];
                c3 += kv4.w * S[u * 4 + 3];
                d0 += qv4.x * S[u * 4 + 0];
                d1 += qv4.y * S[u * 4 + 1];
                d2 += qv4.z * S[u * 4 + 2];
                d3 += qv4.w * S[u * 4 + 3];
            }
            float cpt = (c0 + c1) + (c2 + c3);
            float dpt = (d0 + d1) + (d2 + d3);
            cpt += __shfl_xor_sync(0xffffffffu, cpt, 1);
            cpt += __shfl_xor_sync(0xffffffffu, cpt, 2);
            dpt += __shfl_xor_sync(0xffffffffu, dpt, 1);
            dpt += __shfl_xor_sync(0xffffffffu, dpt, 2);

            // S_t = eg_t * S_{t-1} + k_t * delta_t
#pragma unroll
            for (int j = 0; j < 32; j++)
                S[j] = eg * S[j] + kcur[j] * delta;

            // rotate carried state
            cred = cpt; dred = dpt; dprev = delta; egprev = eg;
        }
    }
}

// ---------------------------------------------------------------------------
// Launch (single stream)
// ---------------------------------------------------------------------------
extern "C" void kernel_launch(void* const* d_in, const int* in_sizes, int n_in,
                              void* d_out, int out_size)
{
    const float* X       = (const float*)d_in[0];
    const float* W       = (const float*)d_in[1];
    const float* Wconv   = (const float*)d_in[2];
    const float* A_log   = (const float*)d_in[3];
    const float* dt_bias = (const float*)d_in[4];
    float* out = (float*)d_out;

    cudaFuncSetAttribute(mma_gemm_kernel,
                         cudaFuncAttributeMaxDynamicSharedMemorySize,
                         SMEM_TOTAL_GEMM);

    split_kernel<<<2048, 256>>>(X, W);

    dim3 gemmGrid(BL / 128, (TOTAL_PROJ + 127) / 128);   // (32, 97)
    mma_gemm_kernel<<<gemmGrid, 256, SMEM_TOTAL_GEMM>>>();

    scalars_kernel<<<(BL * N_HEADS + 255) / 256, 256>>>(A_log, dt_bias);

    dim3 convGrid(CONV_CH / 128, BL / CTILE);
    conv_kernel<<<convGrid, 128>>>(Wconv);

    mnq_kernel<<<8192, 256>>>();

    recurrence_kernel<<<B_SZ * N_HEADS * 4, 256>>>(out);
}